// round 13
// baseline (speedup 1.0000x reference)
#include <cuda_runtime.h>
#include <cuda_fp16.h>
#include <stdint.h>
#include <math.h>

#define BB 8
#define SS 1024
#define DD 1024
#define HH 4096
#define MM (BB*SS)
#define K_SEL 1048576u
#define NPB (SS*HH)
#define NBCAP 64
#define ZCAP 1024
#define RMARG 1.0e-3f

typedef __half h16;

// ---------------- device scratch ----------------
__device__ float g_s2[(size_t)MM * HH];
__device__ h16 g_xh[(size_t)MM * DD], g_xl[(size_t)MM * DD];
__device__ h16 g_w1f[(size_t)HH * DD];
__device__ h16 g_w2f[(size_t)HH * HH];
__device__ h16 g_s1h[(size_t)MM * HH], g_s1l[(size_t)MM * HH];
__device__ h16 g_mdf[(size_t)HH * DD];
__device__ h16 g_dwf[(size_t)DD * HH];
__device__ h16 g_hh[(size_t)MM * HH];
__device__ unsigned g_colmax_u[BB * HH];
__device__ unsigned g_hist[BB * 256];
__device__ unsigned g_prefix[BB], g_rank[BB], g_nb[BB], g_nz[BB];
__device__ int g_blist[BB * NBCAP];
__device__ int g_zlist[BB * ZCAP];
__device__ unsigned char g_mask[BB * HH];

// ---------------- static streams/events (created pre-main, pre-checkpoint) --
struct AuxRes {
    cudaStream_t s = nullptr;
    cudaEvent_t evA = nullptr, evB = nullptr;
    AuxRes() {
        cudaStreamCreateWithFlags(&s, cudaStreamNonBlocking);
        cudaEventCreateWithFlags(&evA, cudaEventDisableTiming);
        cudaEventCreateWithFlags(&evB, cudaEventDisableTiming);
    }
};
static AuxRes g_aux;

// ---------------- PTX helpers (sm_80+ base target only) ----------------
__device__ __forceinline__ uint32_t smem_u32(const void* p) {
    uint32_t a;
    asm("{ .reg .u64 t; cvta.to.shared.u64 t, %1; cvt.u32.u64 %0, t; }"
        : "=r"(a) : "l"(p));
    return a;
}
#define CPA16(dst, src) asm volatile("cp.async.cg.shared.global [%0], [%1], 16;" :: "r"(dst), "l"(src))
#define CPA_COMMIT() asm volatile("cp.async.commit_group;" ::: "memory")
#define CPA_WAIT(N)  asm volatile("cp.async.wait_group %0;" :: "n"(N) : "memory")

__device__ __forceinline__ void ldsm4(uint32_t* r, uint32_t addr) {
    asm volatile("ldmatrix.sync.aligned.m8n8.x4.shared.b16 {%0,%1,%2,%3}, [%4];"
        : "=r"(r[0]), "=r"(r[1]), "=r"(r[2]), "=r"(r[3]) : "r"(addr));
}
__device__ __forceinline__ void mma_h(float* d, const uint32_t* a,
                                      uint32_t b0, uint32_t b1) {
    asm volatile("mma.sync.aligned.m16n8k16.row.col.f32.f16.f16.f32 "
        "{%0,%1,%2,%3}, {%4,%5,%6,%7}, {%8,%9}, {%0,%1,%2,%3};"
        : "+f"(d[0]), "+f"(d[1]), "+f"(d[2]), "+f"(d[3])
        : "r"(a[0]), "r"(a[1]), "r"(a[2]), "r"(a[3]), "r"(b0), "r"(b1));
}
__device__ __forceinline__ unsigned f2u(float f) {
    unsigned u = __float_as_uint(f);
    return (u & 0x80000000u) ? ~u : (u | 0x80000000u);
}
__device__ __forceinline__ float u2f(unsigned v) {
    unsigned u = (v & 0x80000000u) ? (v & 0x7FFFFFFFu) : ~v;
    return __uint_as_float(u);
}

// ---------------- HMMA fp16 split NT GEMM ----------------
// TERMS=1: Ah*Bh   TERMS=2: (Ah+Al)*Bh
// MODE 0: relu(c+bias) -> fp16 pair (C0 hi, C1 lo)
// MODE 1: c+bias -> fp32
// MODE 2: silu(c+bias) -> fp16 C0
// MODE 3: MODE 1 + fused colmax atomicMax + fused radix pass-1 histogram
#define CTM 256
#define CTN 128
#define BKC 64
#define TROW 144

template<int MODE, int TERMS>
__global__ __launch_bounds__(256)
void mma_gemm(const h16* __restrict__ Ah, const h16* __restrict__ Al,
              const h16* __restrict__ Bh,
              const float* __restrict__ bias,
              void* __restrict__ C0, void* __restrict__ C1,
              int Ndim, int Kdim)
{
    constexpr int NA = (TERMS >= 2) ? 2 : 1;
    constexpr int TILE_A = CTM * TROW;
    constexpr int TILE_B = CTN * TROW;
    constexpr int STAGE = NA * TILE_A + TILE_B;
    extern __shared__ __align__(128) char smem[];
    const uint32_t sb = smem_u32(smem);
    const int tid = threadIdx.x;
    const int lane = tid & 31, wid = tid >> 5;
    const int wm = (wid & 3) * 64;
    const int wn = (wid >> 2) * 64;

    const int tiles_n = Ndim / CTN;
    const int per = 8 * tiles_n;
    const int bid = blockIdx.x;
    const int mi = (bid / per) * 8 + (bid % per) % 8;
    const int ni = (bid % per) / 8;
    const int bm = mi * CTM, bn = ni * CTN;

    float acc[4][8][4];
    #pragma unroll
    for (int i = 0; i < 4; i++)
        #pragma unroll
        for (int j = 0; j < 8; j++)
            #pragma unroll
            for (int q = 0; q < 4; q++) acc[i][j][q] = 0.f;

    auto loadA = [&](int s, int k0, const h16* P, int half) {
        const uint32_t base = sb + s * STAGE + half * TILE_A;
        #pragma unroll
        for (int it = 0; it < 8; it++) {
            const int idx = tid + it * 256;
            const int row = idx >> 3, c = idx & 7;
            CPA16(base + row * TROW + c * 16,
                  P + (size_t)(bm + row) * Kdim + k0 + c * 8);
        }
    };
    auto loadB = [&](int s, int k0, const h16* P) {
        const uint32_t base = sb + s * STAGE + NA * TILE_A;
        #pragma unroll
        for (int it = 0; it < 4; it++) {
            const int idx = tid + it * 256;
            const int row = idx >> 3, c = idx & 7;
            CPA16(base + row * TROW + c * 16,
                  P + (size_t)(bn + row) * Kdim + k0 + c * 8);
        }
    };
    auto loadStage = [&](int s, int k0) {
        loadA(s, k0, Ah, 0);
        if (TERMS >= 2) loadA(s, k0, Al, 1);
        loadB(s, k0, Bh);
        CPA_COMMIT();
    };

    const int rsel = lane & 15;
    const int csel = lane >> 4;
    const int C = Kdim / BKC;
    loadStage(0, 0);

    for (int c = 0; c < C; c++) {
        const int s = c & 1;
        if (c + 1 < C) { loadStage(s ^ 1, (c + 1) * BKC); CPA_WAIT(1); }
        else           { CPA_WAIT(0); }
        __syncthreads();

        const uint32_t aH = sb + s * STAGE;
        const uint32_t bH = aH + NA * TILE_A;

        #pragma unroll
        for (int kk = 0; kk < 4; kk++) {
            const int c0 = kk * 2;
            uint32_t af[4][4], bfr[4][4];
            #pragma unroll
            for (int i = 0; i < 4; i++)
                ldsm4(af[i], aH + (uint32_t)((wm + i * 16 + rsel) * TROW + (c0 + csel) * 16));
            #pragma unroll
            for (int g = 0; g < 4; g++)
                ldsm4(bfr[g], bH + (uint32_t)((wn + g * 16 + rsel) * TROW + (c0 + csel) * 16));
            #pragma unroll
            for (int i = 0; i < 4; i++)
                #pragma unroll
                for (int g = 0; g < 4; g++) {
                    mma_h(acc[i][g * 2 + 0], af[i], bfr[g][0], bfr[g][2]);
                    mma_h(acc[i][g * 2 + 1], af[i], bfr[g][1], bfr[g][3]);
                }
            if (TERMS >= 2) {
                uint32_t af2[4][4];
                #pragma unroll
                for (int i = 0; i < 4; i++)
                    ldsm4(af2[i], aH + TILE_A + (uint32_t)((wm + i * 16 + rsel) * TROW + (c0 + csel) * 16));
                #pragma unroll
                for (int i = 0; i < 4; i++)
                    #pragma unroll
                    for (int g = 0; g < 4; g++) {
                        mma_h(acc[i][g * 2 + 0], af2[i], bfr[g][0], bfr[g][2]);
                        mma_h(acc[i][g * 2 + 1], af2[i], bfr[g][1], bfr[g][3]);
                    }
            }
        }
        __syncthreads();
    }

    // ---------------- epilogue ----------------
    unsigned* shist = (unsigned*)smem;
    if (MODE == 3) {
        for (int i = tid; i < 256; i += 256) shist[i] = 0u;
        __syncthreads();
    }

    const int t4 = lane >> 2;
    const int tn2 = (lane & 3) * 2;
    #pragma unroll
    for (int i = 0; i < 4; i++) {
        #pragma unroll
        for (int j = 0; j < 8; j++) {
            const int m = bm + wm + i * 16 + t4;
            const int n = bn + wn + j * 8 + tn2;
            const float b0 = __ldg(bias + n), b1 = __ldg(bias + n + 1);
            float v0 = acc[i][j][0] + b0, v1 = acc[i][j][1] + b1;
            float v2 = acc[i][j][2] + b0, v3 = acc[i][j][3] + b1;
            if (MODE == 1 || MODE == 3) {
                float* o0 = (float*)C0 + (size_t)m * Ndim + n;
                float* o1 = (float*)C0 + (size_t)(m + 8) * Ndim + n;
                *(float2*)o0 = make_float2(v0, v1);
                *(float2*)o1 = make_float2(v2, v3);
                if (MODE == 3) {
                    atomicAdd(&shist[f2u(v0) >> 24], 1u);
                    atomicAdd(&shist[f2u(v1) >> 24], 1u);
                    atomicAdd(&shist[f2u(v2) >> 24], 1u);
                    atomicAdd(&shist[f2u(v3) >> 24], 1u);
                }
            } else {
                if (MODE == 0) {
                    v0 = fmaxf(v0, 0.f); v1 = fmaxf(v1, 0.f);
                    v2 = fmaxf(v2, 0.f); v3 = fmaxf(v3, 0.f);
                } else {
                    v0 = v0 / (1.f + expf(-v0)); v1 = v1 / (1.f + expf(-v1));
                    v2 = v2 / (1.f + expf(-v2)); v3 = v3 / (1.f + expf(-v3));
                }
                h16 h0 = __float2half_rn(v0), h1 = __float2half_rn(v1);
                h16 h2 = __float2half_rn(v2), h3 = __float2half_rn(v3);
                h16* oh0 = (h16*)C0 + (size_t)m * Ndim + n;
                h16* oh1 = (h16*)C0 + (size_t)(m + 8) * Ndim + n;
                *(__half2*)oh0 = __halves2half2(h0, h1);
                *(__half2*)oh1 = __halves2half2(h2, h3);
                if (MODE == 0) {
                    h16 l0 = __float2half_rn(v0 - __half2float(h0));
                    h16 l1 = __float2half_rn(v1 - __half2float(h1));
                    h16 l2 = __float2half_rn(v2 - __half2float(h2));
                    h16 l3 = __float2half_rn(v3 - __half2float(h3));
                    h16* ol0 = (h16*)C1 + (size_t)m * Ndim + n;
                    h16* ol1 = (h16*)C1 + (size_t)(m + 8) * Ndim + n;
                    *(__half2*)ol0 = __halves2half2(l0, l1);
                    *(__half2*)ol1 = __halves2half2(l2, l3);
                }
            }
        }
    }

    if (MODE == 3) {
        const int b = bm >> 10;
        __syncthreads();
        if (tid < 256 && shist[tid]) atomicAdd(&g_hist[b * 256 + tid], shist[tid]);
        #pragma unroll
        for (int j = 0; j < 8; j++) {
            const int n = bn + wn + j * 8 + tn2;
            #pragma unroll
            for (int q = 0; q < 2; q++) {
                float vmax = -3.4e38f;
                #pragma unroll
                for (int i = 0; i < 4; i++)
                    vmax = fmaxf(vmax, fmaxf(acc[i][j][q], acc[i][j][q + 2]));
                vmax += __ldg(bias + n + q);
                #pragma unroll
                for (int o = 4; o <= 16; o <<= 1)
                    vmax = fmaxf(vmax, __shfl_xor_sync(0xFFFFFFFFu, vmax, o));
                if (t4 == 0)
                    atomicMax(&g_colmax_u[b * HH + n + q], f2u(vmax));
            }
        }
    }
}

// ---------------- conversion kernels ----------------
__global__ void cvtp_kernel(const float* __restrict__ s,
                            h16* __restrict__ dh, h16* __restrict__ dl) {
    const int i = (blockIdx.x * 256 + threadIdx.x) * 4;
    float4 v = *(const float4*)(s + i);
    h16 a0 = __float2half_rn(v.x), a1 = __float2half_rn(v.y);
    h16 a2 = __float2half_rn(v.z), a3 = __float2half_rn(v.w);
    *(__half2*)(dh + i)     = __halves2half2(a0, a1);
    *(__half2*)(dh + i + 2) = __halves2half2(a2, a3);
    *(__half2*)(dl + i)     = __halves2half2(
        __float2half_rn(v.x - __half2float(a0)),
        __float2half_rn(v.y - __half2float(a1)));
    *(__half2*)(dl + i + 2) = __halves2half2(
        __float2half_rn(v.z - __half2float(a2)),
        __float2half_rn(v.w - __half2float(a3)));
}
__global__ void cvt1_kernel(const float* __restrict__ s, h16* __restrict__ d) {
    const int i = (blockIdx.x * 256 + threadIdx.x) * 4;
    float4 v = *(const float4*)(s + i);
    *(__half2*)(d + i)     = __halves2half2(__float2half_rn(v.x), __float2half_rn(v.y));
    *(__half2*)(d + i + 2) = __halves2half2(__float2half_rn(v.z), __float2half_rn(v.w));
}

// ---------------- selection machinery ----------------
__global__ void select_init_kernel() {
    const int t = blockIdx.x * 256 + threadIdx.x;
    if (t < BB * HH) g_colmax_u[t] = 0u;
    if (t < BB * 256) g_hist[t] = 0u;
    if (t < BB) { g_prefix[t] = 0u; g_rank[t] = K_SEL; g_nb[t] = 0u; g_nz[t] = 0u; }
}

__global__ void hist_kernel(const float* __restrict__ s2, int shift) {
    __shared__ unsigned sh[256];
    const int b = blockIdx.y;
    sh[threadIdx.x] = 0u;
    __syncthreads();
    const unsigned pref = g_prefix[b];
    const float* p = s2 + (size_t)b * NPB;
    const int base = blockIdx.x * 2048;
    #pragma unroll
    for (int i = 0; i < 8; i++) {
        const unsigned u = f2u(p[base + i * 256 + threadIdx.x]);
        const unsigned hi = u >> (shift + 8);
        if (hi == pref) atomicAdd(&sh[(u >> shift) & 255u], 1u);
    }
    __syncthreads();
    if (sh[threadIdx.x]) atomicAdd(&g_hist[b * 256 + threadIdx.x], sh[threadIdx.x]);
}

// parallel scan: suffix sums + digit select (grid BB, 256 thr)
__global__ void scan2_kernel() {
    __shared__ unsigned suf[256];
    __shared__ int dsel;
    const int b = blockIdx.x, t = threadIdx.x;
    suf[t] = g_hist[b * 256 + t];
    if (t == 0) dsel = 0;
    __syncthreads();
    for (int off = 1; off < 256; off <<= 1) {
        unsigned add = (t + off < 256) ? suf[t + off] : 0u;
        __syncthreads();
        suf[t] += add;
        __syncthreads();
    }
    const unsigned r = g_rank[b];
    if (suf[t] >= r) atomicMax(&dsel, t);
    __syncthreads();
    if (t == 0) {
        const int d = dsel;
        const unsigned sub = (d < 255) ? suf[d + 1] : 0u;
        g_rank[b] = r - sub;
        g_prefix[b] = (g_prefix[b] << 8) | (unsigned)d;
    }
    g_hist[b * 256 + t] = 0u;
}

// provisional mask + borderline flagging
__global__ void flag_kernel() {
    const int i = blockIdx.x * 256 + threadIdx.x;
    const int b = i >> 12;
    const unsigned tu = g_prefix[b];
    const unsigned cu = g_colmax_u[i];
    g_mask[i] = (cu >= tu) ? (unsigned char)1 : (unsigned char)0;
    if (fabsf(u2f(cu) - u2f(tu)) < RMARG) {
        const unsigned idx = atomicAdd(&g_nb[b], 1u);
        if (idx < NBCAP) g_blist[b * NBCAP + idx] = i & (HH - 1);
    }
}

// exact fp32 recompute of borderline columns
__global__ __launch_bounds__(1024)
void refine_kernel(const h16* __restrict__ s1h, const h16* __restrict__ s1l,
                   const float* __restrict__ w2, const float* __restrict__ b2)
{
    const int b = blockIdx.x / NBCAP;
    const int j = blockIdx.x % NBCAP;
    const unsigned nb = min(g_nb[b], (unsigned)NBCAP);
    if (j >= (int)nb) return;
    const int h = g_blist[b * NBCAP + j];

    __shared__ float w2s[HH];
    __shared__ float wmax[32];
    const int tid = threadIdx.x;
    const int lane = tid & 31, wid = tid >> 5;
    for (int k = tid; k < HH; k += 1024) w2s[k] = w2[(size_t)h * HH + k];
    __syncthreads();

    float vmax = -3.4e38f;
    for (int s = wid; s < SS; s += 32) {
        const size_t roff = ((size_t)b * SS + s) * HH;
        const __half2* ph = (const __half2*)(s1h + roff);
        const __half2* pl = (const __half2*)(s1l + roff);
        float part = 0.f;
        for (int k2 = lane; k2 < HH / 2; k2 += 32) {
            const __half2 vh = ph[k2], vl = pl[k2];
            part += (__half2float(vh.x) + __half2float(vl.x)) * w2s[k2 * 2];
            part += (__half2float(vh.y) + __half2float(vl.y)) * w2s[k2 * 2 + 1];
        }
        #pragma unroll
        for (int o = 16; o >= 1; o >>= 1)
            part += __shfl_xor_sync(0xFFFFFFFFu, part, o);
        vmax = fmaxf(vmax, part);
    }
    if (lane == 0) wmax[wid] = vmax;
    __syncthreads();
    if (tid == 0) {
        float m = wmax[0];
        #pragma unroll
        for (int w = 1; w < 32; w++) m = fmaxf(m, wmax[w]);
        m += b2[h];
        g_mask[b * HH + h] = (f2u(m) >= g_prefix[b]) ? (unsigned char)1 : (unsigned char)0;
    }
}

// collect mask==0 columns (final mask, post-refine)
__global__ void zlist_kernel() {
    const int i = blockIdx.x * 256 + threadIdx.x;
    const int b = i >> 12;
    if (!g_mask[i]) {
        const unsigned idx = atomicAdd(&g_nz[b], 1u);
        if (idx < ZCAP) g_zlist[b * ZCAP + idx] = i & (HH - 1);
    }
}

// recompute h for mask==0 columns with fp32 up_w path
__global__ __launch_bounds__(256)
void patch_kernel(const float* __restrict__ X, const float* __restrict__ upw,
                  const float* __restrict__ upb, h16* __restrict__ hh)
{
    const int b = blockIdx.x >> 10;
    const int j = blockIdx.x & (ZCAP - 1);
    const unsigned nz = min(g_nz[b], (unsigned)ZCAP);
    if (j >= (int)nz) return;
    const int h0 = g_zlist[b * ZCAP + j];

    __shared__ float w[DD];
    const int tid = threadIdx.x, lane = tid & 31, wid = tid >> 5;
    for (int k = tid; k < DD; k += 256) w[k] = upw[(size_t)h0 * DD + k];
    __syncthreads();
    const float bv = upb[h0];

    for (int s = wid; s < SS; s += 8) {
        const float* row = X + ((size_t)b * SS + s) * DD;
        float p = 0.f;
        for (int k = lane; k < DD; k += 32) p += row[k] * w[k];
        #pragma unroll
        for (int o = 16; o >= 1; o >>= 1)
            p += __shfl_xor_sync(0xFFFFFFFFu, p, o);
        if (lane == 0) {
            float v = p + bv;
            v = v / (1.f + expf(-v));
            hh[((size_t)b * SS + s) * HH + h0] = __float2half_rn(v);
        }
    }
}

// ---------------- launch ----------------
extern "C" void kernel_launch(void* const* d_in, const int* in_sizes, int n_in,
                              void* d_out, int out_size)
{
    (void)in_sizes; (void)n_in; (void)out_size;
    const float* inputs  = (const float*)d_in[0];
    const float* up_w    = (const float*)d_in[1];
    const float* up_b    = (const float*)d_in[2];
    const float* gate_w1 = (const float*)d_in[3];
    const float* gate_b1 = (const float*)d_in[4];
    const float* gate_w2 = (const float*)d_in[5];
    const float* gate_b2 = (const float*)d_in[6];
    const float* mod_w   = (const float*)d_in[7];
    const float* mod_b   = (const float*)d_in[8];
    const float* down_w  = (const float*)d_in[9];
    const float* down_b  = (const float*)d_in[10];
    float* out = (float*)d_out;

    float* s2;
    h16 *xh, *xl, *w1f, *w2f, *s1h, *s1l, *mdf, *dwf, *hh;
    cudaGetSymbolAddress((void**)&s2,  g_s2);
    cudaGetSymbolAddress((void**)&xh,  g_xh);
    cudaGetSymbolAddress((void**)&xl,  g_xl);
    cudaGetSymbolAddress((void**)&w1f, g_w1f);
    cudaGetSymbolAddress((void**)&w2f, g_w2f);
    cudaGetSymbolAddress((void**)&s1h, g_s1h);
    cudaGetSymbolAddress((void**)&s1l, g_s1l);
    cudaGetSymbolAddress((void**)&mdf, g_mdf);
    cudaGetSymbolAddress((void**)&dwf, g_dwf);
    cudaGetSymbolAddress((void**)&hh,  g_hh);

    const int SM2 = 2 * (2 * CTM * TROW + 1 * CTN * TROW);   // 184320
    const int SM1 = 2 * (1 * CTM * TROW + 1 * CTN * TROW);   // 110592
    cudaFuncSetAttribute(mma_gemm<0, 2>, cudaFuncAttributeMaxDynamicSharedMemorySize, SM2);
    cudaFuncSetAttribute(mma_gemm<3, 1>, cudaFuncAttributeMaxDynamicSharedMemorySize, SM1);
    cudaFuncSetAttribute(mma_gemm<2, 1>, cudaFuncAttributeMaxDynamicSharedMemorySize, SM1);
    cudaFuncSetAttribute(mma_gemm<1, 1>, cudaFuncAttributeMaxDynamicSharedMemorySize, SM1);

    // ---- main chain (default stream) ----
    cvtp_kernel<<<(MM * DD) / 1024, 256>>>(inputs, xh, xl);
    cvt1_kernel<<<(HH * DD) / 1024, 256>>>(gate_w1, w1f);
    cvt1_kernel<<<(HH * HH) / 1024, 256>>>(gate_w2, w2f);
    select_init_kernel<<<BB * HH / 256, 256>>>();

    // G1: scores1 = relu(X @ W1^T + b1) -> fp16 pair (2-term)
    mma_gemm<0, 2><<<(MM / CTM) * (HH / CTN), 256, SM2>>>(
        xh, xl, w1f, gate_b1, s1h, s1l, HH, DD);

    // G2: scores2 -> fp32 + fused colmax + fused radix pass-1 (1-term)
    mma_gemm<3, 1><<<(MM / CTM) * (HH / CTN), 256, SM1>>>(
        s1h, nullptr, w2f, gate_b2, s2, nullptr, HH, HH);

    // ---- fork: aux branch = value path (independent of selection) ----
    cudaEventRecord(g_aux.evA, 0);
    cudaStreamWaitEvent(g_aux.s, g_aux.evA, 0);
    cvt1_kernel<<<(HH * DD) / 1024, 256, 0, g_aux.s>>>(mod_w, mdf);
    cvt1_kernel<<<(DD * HH) / 1024, 256, 0, g_aux.s>>>(down_w, dwf);
    // G4-base: h = silu(X @ mod_w^T + mod_b), all columns (mask-free)
    mma_gemm<2, 1><<<(MM / CTM) * (HH / CTN), 256, SM1, g_aux.s>>>(
        xh, nullptr, mdf, mod_b, hh, nullptr, HH, DD);
    cudaEventRecord(g_aux.evB, g_aux.s);

    // ---- selection chain (default stream), overlapped with aux ----
    scan2_kernel<<<BB, 256>>>();
    for (int p = 0; p < 3; p++) {
        dim3 grid(NPB / 2048, BB);
        hist_kernel<<<grid, 256>>>(s2, 16 - 8 * p);
        scan2_kernel<<<BB, 256>>>();
    }
    flag_kernel<<<BB * HH / 256, 256>>>();
    refine_kernel<<<BB * NBCAP, 1024>>>(s1h, s1l, gate_w2, gate_b2);
    zlist_kernel<<<BB * HH / 256, 256>>>();

    // ---- join: patch mask==0 columns, then G5 ----
    cudaStreamWaitEvent(0, g_aux.evB, 0);
    patch_kernel<<<BB * ZCAP, 256>>>(inputs, up_w, up_b, hh);

    // G5: out = h @ Wd^T + bd -> fp32 (1-term)
    mma_gemm<1, 1><<<(MM / CTM) * (DD / CTN), 256, SM1>>>(
        hh, nullptr, dwf, down_b, out, nullptr, DD, HH);
}

// round 14
// speedup vs baseline: 1.0306x; 1.0306x over previous
#include <cuda_runtime.h>
#include <cuda_fp16.h>
#include <stdint.h>
#include <math.h>

#define BB 8
#define SS 1024
#define DD 1024
#define HH 4096
#define MM (BB*SS)
#define K_SEL 1048576u
#define NPB (SS*HH)
#define NBCAP 64
#define ZCAP 1024
#define RMARG 1.0e-3f
#define NBIN 4096

typedef __half h16;

// ---------------- device scratch ----------------
__device__ float g_s2[(size_t)MM * HH];
__device__ h16 g_xh[(size_t)MM * DD], g_xl[(size_t)MM * DD];
__device__ h16 g_w1f[(size_t)HH * DD];
__device__ h16 g_w2f[(size_t)HH * HH];
__device__ h16 g_s1h[(size_t)MM * HH], g_s1l[(size_t)MM * HH];
__device__ h16 g_mdf[(size_t)HH * DD];
__device__ h16 g_dwf[(size_t)DD * HH];
__device__ h16 g_hh[(size_t)MM * HH];
__device__ unsigned g_colmax_u[BB * HH];
__device__ unsigned g_hist[BB * NBIN];
__device__ unsigned g_prefix[BB], g_rank[BB], g_nb[BB], g_nz[BB];
__device__ int g_blist[BB * NBCAP];
__device__ int g_zlist[BB * ZCAP];
__device__ unsigned char g_mask[BB * HH];

// ---------------- PTX helpers (sm_80+ base target only) ----------------
__device__ __forceinline__ uint32_t smem_u32(const void* p) {
    uint32_t a;
    asm("{ .reg .u64 t; cvta.to.shared.u64 t, %1; cvt.u32.u64 %0, t; }"
        : "=r"(a) : "l"(p));
    return a;
}
#define CPA16(dst, src) asm volatile("cp.async.cg.shared.global [%0], [%1], 16;" :: "r"(dst), "l"(src))
#define CPA_COMMIT() asm volatile("cp.async.commit_group;" ::: "memory")
#define CPA_WAIT(N)  asm volatile("cp.async.wait_group %0;" :: "n"(N) : "memory")

__device__ __forceinline__ void ldsm4(uint32_t* r, uint32_t addr) {
    asm volatile("ldmatrix.sync.aligned.m8n8.x4.shared.b16 {%0,%1,%2,%3}, [%4];"
        : "=r"(r[0]), "=r"(r[1]), "=r"(r[2]), "=r"(r[3]) : "r"(addr));
}
__device__ __forceinline__ void mma_h(float* d, const uint32_t* a,
                                      uint32_t b0, uint32_t b1) {
    asm volatile("mma.sync.aligned.m16n8k16.row.col.f32.f16.f16.f32 "
        "{%0,%1,%2,%3}, {%4,%5,%6,%7}, {%8,%9}, {%0,%1,%2,%3};"
        : "+f"(d[0]), "+f"(d[1]), "+f"(d[2]), "+f"(d[3])
        : "r"(a[0]), "r"(a[1]), "r"(a[2]), "r"(a[3]), "r"(b0), "r"(b1));
}
__device__ __forceinline__ unsigned f2u(float f) {
    unsigned u = __float_as_uint(f);
    return (u & 0x80000000u) ? ~u : (u | 0x80000000u);
}
__device__ __forceinline__ float u2f(unsigned v) {
    unsigned u = (v & 0x80000000u) ? (v & 0x7FFFFFFFu) : ~v;
    return __uint_as_float(u);
}

// ---------------- HMMA fp16 split NT GEMM ----------------
// TERMS=1: Ah*Bh   TERMS=2: (Ah+Al)*Bh
// MODE 0: relu(c+bias) -> fp16 pair (C0 hi, C1 lo)
// MODE 1: c+bias -> fp32
// MODE 2: silu(c+bias) -> fp16 C0
// MODE 3: MODE 1 + fused colmax atomicMax + fused 12-bit radix pass-1
#define CTM 256
#define CTN 128
#define BKC 64
#define TROW 144

template<int MODE, int TERMS>
__global__ __launch_bounds__(256)
void mma_gemm(const h16* __restrict__ Ah, const h16* __restrict__ Al,
              const h16* __restrict__ Bh,
              const float* __restrict__ bias,
              void* __restrict__ C0, void* __restrict__ C1,
              int Ndim, int Kdim)
{
    constexpr int NA = (TERMS >= 2) ? 2 : 1;
    constexpr int TILE_A = CTM * TROW;
    constexpr int TILE_B = CTN * TROW;
    constexpr int STAGE = NA * TILE_A + TILE_B;
    extern __shared__ __align__(128) char smem[];
    const uint32_t sb = smem_u32(smem);
    const int tid = threadIdx.x;
    const int lane = tid & 31, wid = tid >> 5;
    const int wm = (wid & 3) * 64;
    const int wn = (wid >> 2) * 64;

    const int tiles_n = Ndim / CTN;
    const int per = 8 * tiles_n;
    const int bid = blockIdx.x;
    const int mi = (bid / per) * 8 + (bid % per) % 8;
    const int ni = (bid % per) / 8;
    const int bm = mi * CTM, bn = ni * CTN;

    float acc[4][8][4];
    #pragma unroll
    for (int i = 0; i < 4; i++)
        #pragma unroll
        for (int j = 0; j < 8; j++)
            #pragma unroll
            for (int q = 0; q < 4; q++) acc[i][j][q] = 0.f;

    auto loadA = [&](int s, int k0, const h16* P, int half) {
        const uint32_t base = sb + s * STAGE + half * TILE_A;
        #pragma unroll
        for (int it = 0; it < 8; it++) {
            const int idx = tid + it * 256;
            const int row = idx >> 3, c = idx & 7;
            CPA16(base + row * TROW + c * 16,
                  P + (size_t)(bm + row) * Kdim + k0 + c * 8);
        }
    };
    auto loadB = [&](int s, int k0, const h16* P) {
        const uint32_t base = sb + s * STAGE + NA * TILE_A;
        #pragma unroll
        for (int it = 0; it < 4; it++) {
            const int idx = tid + it * 256;
            const int row = idx >> 3, c = idx & 7;
            CPA16(base + row * TROW + c * 16,
                  P + (size_t)(bn + row) * Kdim + k0 + c * 8);
        }
    };
    auto loadStage = [&](int s, int k0) {
        loadA(s, k0, Ah, 0);
        if (TERMS >= 2) loadA(s, k0, Al, 1);
        loadB(s, k0, Bh);
        CPA_COMMIT();
    };

    const int rsel = lane & 15;
    const int csel = lane >> 4;
    const int C = Kdim / BKC;
    loadStage(0, 0);

    for (int c = 0; c < C; c++) {
        const int s = c & 1;
        if (c + 1 < C) { loadStage(s ^ 1, (c + 1) * BKC); CPA_WAIT(1); }
        else           { CPA_WAIT(0); }
        __syncthreads();

        const uint32_t aH = sb + s * STAGE;
        const uint32_t bH = aH + NA * TILE_A;

        #pragma unroll
        for (int kk = 0; kk < 4; kk++) {
            const int c0 = kk * 2;
            uint32_t af[4][4], bfr[4][4];
            #pragma unroll
            for (int i = 0; i < 4; i++)
                ldsm4(af[i], aH + (uint32_t)((wm + i * 16 + rsel) * TROW + (c0 + csel) * 16));
            #pragma unroll
            for (int g = 0; g < 4; g++)
                ldsm4(bfr[g], bH + (uint32_t)((wn + g * 16 + rsel) * TROW + (c0 + csel) * 16));
            #pragma unroll
            for (int i = 0; i < 4; i++)
                #pragma unroll
                for (int g = 0; g < 4; g++) {
                    mma_h(acc[i][g * 2 + 0], af[i], bfr[g][0], bfr[g][2]);
                    mma_h(acc[i][g * 2 + 1], af[i], bfr[g][1], bfr[g][3]);
                }
            if (TERMS >= 2) {
                uint32_t af2[4][4];
                #pragma unroll
                for (int i = 0; i < 4; i++)
                    ldsm4(af2[i], aH + TILE_A + (uint32_t)((wm + i * 16 + rsel) * TROW + (c0 + csel) * 16));
                #pragma unroll
                for (int i = 0; i < 4; i++)
                    #pragma unroll
                    for (int g = 0; g < 4; g++) {
                        mma_h(acc[i][g * 2 + 0], af2[i], bfr[g][0], bfr[g][2]);
                        mma_h(acc[i][g * 2 + 1], af2[i], bfr[g][1], bfr[g][3]);
                    }
            }
        }
        __syncthreads();
    }

    // ---------------- epilogue ----------------
    unsigned* shist = (unsigned*)smem;       // 4096 bins, reuses stage smem
    if (MODE == 3) {
        for (int i = tid; i < NBIN; i += 256) shist[i] = 0u;
        __syncthreads();
    }

    const int t4 = lane >> 2;
    const int tn2 = (lane & 3) * 2;
    #pragma unroll
    for (int i = 0; i < 4; i++) {
        #pragma unroll
        for (int j = 0; j < 8; j++) {
            const int m = bm + wm + i * 16 + t4;
            const int n = bn + wn + j * 8 + tn2;
            const float b0 = __ldg(bias + n), b1 = __ldg(bias + n + 1);
            float v0 = acc[i][j][0] + b0, v1 = acc[i][j][1] + b1;
            float v2 = acc[i][j][2] + b0, v3 = acc[i][j][3] + b1;
            if (MODE == 1 || MODE == 3) {
                float* o0 = (float*)C0 + (size_t)m * Ndim + n;
                float* o1 = (float*)C0 + (size_t)(m + 8) * Ndim + n;
                *(float2*)o0 = make_float2(v0, v1);
                *(float2*)o1 = make_float2(v2, v3);
                if (MODE == 3) {
                    atomicAdd(&shist[f2u(v0) >> 20], 1u);
                    atomicAdd(&shist[f2u(v1) >> 20], 1u);
                    atomicAdd(&shist[f2u(v2) >> 20], 1u);
                    atomicAdd(&shist[f2u(v3) >> 20], 1u);
                }
            } else {
                if (MODE == 0) {
                    v0 = fmaxf(v0, 0.f); v1 = fmaxf(v1, 0.f);
                    v2 = fmaxf(v2, 0.f); v3 = fmaxf(v3, 0.f);
                } else {
                    v0 = v0 / (1.f + expf(-v0)); v1 = v1 / (1.f + expf(-v1));
                    v2 = v2 / (1.f + expf(-v2)); v3 = v3 / (1.f + expf(-v3));
                }
                h16 h0 = __float2half_rn(v0), h1 = __float2half_rn(v1);
                h16 h2 = __float2half_rn(v2), h3 = __float2half_rn(v3);
                h16* oh0 = (h16*)C0 + (size_t)m * Ndim + n;
                h16* oh1 = (h16*)C0 + (size_t)(m + 8) * Ndim + n;
                *(__half2*)oh0 = __halves2half2(h0, h1);
                *(__half2*)oh1 = __halves2half2(h2, h3);
                if (MODE == 0) {
                    h16 l0 = __float2half_rn(v0 - __half2float(h0));
                    h16 l1 = __float2half_rn(v1 - __half2float(h1));
                    h16 l2 = __float2half_rn(v2 - __half2float(h2));
                    h16 l3 = __float2half_rn(v3 - __half2float(h3));
                    h16* ol0 = (h16*)C1 + (size_t)m * Ndim + n;
                    h16* ol1 = (h16*)C1 + (size_t)(m + 8) * Ndim + n;
                    *(__half2*)ol0 = __halves2half2(l0, l1);
                    *(__half2*)ol1 = __halves2half2(l2, l3);
                }
            }
        }
    }

    if (MODE == 3) {
        const int b = bm >> 10;
        __syncthreads();
        for (int i = tid; i < NBIN; i += 256)
            if (shist[i]) atomicAdd(&g_hist[b * NBIN + i], shist[i]);
        #pragma unroll
        for (int j = 0; j < 8; j++) {
            const int n = bn + wn + j * 8 + tn2;
            #pragma unroll
            for (int q = 0; q < 2; q++) {
                float vmax = -3.4e38f;
                #pragma unroll
                for (int i = 0; i < 4; i++)
                    vmax = fmaxf(vmax, fmaxf(acc[i][j][q], acc[i][j][q + 2]));
                vmax += __ldg(bias + n + q);
                #pragma unroll
                for (int o = 4; o <= 16; o <<= 1)
                    vmax = fmaxf(vmax, __shfl_xor_sync(0xFFFFFFFFu, vmax, o));
                if (t4 == 0)
                    atomicMax(&g_colmax_u[b * HH + n + q], f2u(vmax));
            }
        }
    }
}

// ---------------- conversion kernels ----------------
__global__ void cvtp_kernel(const float* __restrict__ s,
                            h16* __restrict__ dh, h16* __restrict__ dl) {
    const int i = (blockIdx.x * 256 + threadIdx.x) * 4;
    float4 v = *(const float4*)(s + i);
    h16 a0 = __float2half_rn(v.x), a1 = __float2half_rn(v.y);
    h16 a2 = __float2half_rn(v.z), a3 = __float2half_rn(v.w);
    *(__half2*)(dh + i)     = __halves2half2(a0, a1);
    *(__half2*)(dh + i + 2) = __halves2half2(a2, a3);
    *(__half2*)(dl + i)     = __halves2half2(
        __float2half_rn(v.x - __half2float(a0)),
        __float2half_rn(v.y - __half2float(a1)));
    *(__half2*)(dl + i + 2) = __halves2half2(
        __float2half_rn(v.z - __half2float(a2)),
        __float2half_rn(v.w - __half2float(a3)));
}
__global__ void cvt1_kernel(const float* __restrict__ s, h16* __restrict__ d) {
    const int i = (blockIdx.x * 256 + threadIdx.x) * 4;
    float4 v = *(const float4*)(s + i);
    *(__half2*)(d + i)     = __halves2half2(__float2half_rn(v.x), __float2half_rn(v.y));
    *(__half2*)(d + i + 2) = __halves2half2(__float2half_rn(v.z), __float2half_rn(v.w));
}

// ---------------- selection machinery ----------------
__global__ void select_init_kernel() {
    const int t = blockIdx.x * 256 + threadIdx.x;       // 32768 threads
    if (t < BB * HH) g_colmax_u[t] = 0u;
    if (t < BB * NBIN) g_hist[t] = 0u;
    if (t < BB) { g_prefix[t] = 0u; g_rank[t] = K_SEL; g_nb[t] = 0u; g_nz[t] = 0u; }
}

// pass-2 histogram: bits [8:20) of elements whose top-12 match prefix
__global__ void hist12_kernel(const float* __restrict__ s2) {
    __shared__ unsigned sh[NBIN];
    const int b = blockIdx.y;
    const int tid = threadIdx.x;
    for (int i = tid; i < NBIN; i += 256) sh[i] = 0u;
    __syncthreads();
    const unsigned pref = g_prefix[b];
    const float* p = s2 + (size_t)b * NPB;
    const int base = blockIdx.x * 16384;
    #pragma unroll
    for (int i = 0; i < 64; i++) {
        const unsigned u = f2u(p[base + i * 256 + tid]);
        if ((u >> 20) == pref) atomicAdd(&sh[(u >> 8) & 0xFFFu], 1u);
    }
    __syncthreads();
    for (int i = tid; i < NBIN; i += 256)
        if (sh[i]) atomicAdd(&g_hist[b * NBIN + i], sh[i]);
}

// parallel digit select over 4096 bins (grid BB, 256 thr, 16 bins/thread)
__global__ void scan12_kernel(int final) {
    __shared__ unsigned csum[256];
    __shared__ int dsel;
    const int b = blockIdx.x, t = threadIdx.x;
    unsigned loc[16], s = 0;
    const int base = b * NBIN + t * 16;
    #pragma unroll
    for (int i = 0; i < 16; i++) { loc[i] = g_hist[base + i]; s += loc[i]; }
    csum[t] = s;
    if (t == 0) dsel = -1;
    __syncthreads();
    for (int off = 1; off < 256; off <<= 1) {
        unsigned add = (t + off < 256) ? csum[t + off] : 0u;
        __syncthreads();
        csum[t] += add;
        __syncthreads();
    }
    const unsigned r = g_rank[b];
    const unsigned above = (t + 1 < 256) ? csum[t + 1] : 0u;
    unsigned run = above;
    int mydi = -1; unsigned mysub = 0;
    for (int i = 15; i >= 0; i--) {
        run += loc[i];
        if (run >= r) { mydi = i; mysub = run - loc[i]; break; }
    }
    if (mydi >= 0) atomicMax(&dsel, t * 16 + mydi);
    __syncthreads();
    if (mydi >= 0 && t * 16 + mydi == dsel) {
        g_rank[b] = r - mysub;
        if (final) g_prefix[b] = ((g_prefix[b] << 12) | (unsigned)dsel) << 8;
        else       g_prefix[b] = (unsigned)dsel;
    }
    #pragma unroll
    for (int i = 0; i < 16; i++) g_hist[base + i] = 0u;
}

// provisional mask + borderline flagging (g_prefix = final tu)
__global__ void flag_kernel() {
    const int i = blockIdx.x * 256 + threadIdx.x;
    const int b = i >> 12;
    const unsigned tu = g_prefix[b];
    const unsigned cu = g_colmax_u[i];
    g_mask[i] = (cu >= tu) ? (unsigned char)1 : (unsigned char)0;
    if (fabsf(u2f(cu) - u2f(tu)) < RMARG) {
        const unsigned idx = atomicAdd(&g_nb[b], 1u);
        if (idx < NBCAP) g_blist[b * NBCAP + idx] = i & (HH - 1);
    }
}

// exact fp32 recompute of borderline columns
__global__ __launch_bounds__(1024)
void refine_kernel(const h16* __restrict__ s1h, const h16* __restrict__ s1l,
                   const float* __restrict__ w2, const float* __restrict__ b2)
{
    const int b = blockIdx.x / NBCAP;
    const int j = blockIdx.x % NBCAP;
    const unsigned nb = min(g_nb[b], (unsigned)NBCAP);
    if (j >= (int)nb) return;
    const int h = g_blist[b * NBCAP + j];

    __shared__ float w2s[HH];
    __shared__ float wmax[32];
    const int tid = threadIdx.x;
    const int lane = tid & 31, wid = tid >> 5;
    for (int k = tid; k < HH; k += 1024) w2s[k] = w2[(size_t)h * HH + k];
    __syncthreads();

    float vmax = -3.4e38f;
    for (int s = wid; s < SS; s += 32) {
        const size_t roff = ((size_t)b * SS + s) * HH;
        const __half2* ph = (const __half2*)(s1h + roff);
        const __half2* pl = (const __half2*)(s1l + roff);
        float part = 0.f;
        for (int k2 = lane; k2 < HH / 2; k2 += 32) {
            const __half2 vh = ph[k2], vl = pl[k2];
            part += (__half2float(vh.x) + __half2float(vl.x)) * w2s[k2 * 2];
            part += (__half2float(vh.y) + __half2float(vl.y)) * w2s[k2 * 2 + 1];
        }
        #pragma unroll
        for (int o = 16; o >= 1; o >>= 1)
            part += __shfl_xor_sync(0xFFFFFFFFu, part, o);
        vmax = fmaxf(vmax, part);
    }
    if (lane == 0) wmax[wid] = vmax;
    __syncthreads();
    if (tid == 0) {
        float m = wmax[0];
        #pragma unroll
        for (int w = 1; w < 32; w++) m = fmaxf(m, wmax[w]);
        m += b2[h];
        g_mask[b * HH + h] = (f2u(m) >= g_prefix[b]) ? (unsigned char)1 : (unsigned char)0;
    }
}

// collect mask==0 columns (final mask, post-refine)
__global__ void zlist_kernel() {
    const int i = blockIdx.x * 256 + threadIdx.x;
    const int b = i >> 12;
    if (!g_mask[i]) {
        const unsigned idx = atomicAdd(&g_nz[b], 1u);
        if (idx < ZCAP) g_zlist[b * ZCAP + idx] = i & (HH - 1);
    }
}

// recompute h for mask==0 columns with fp32 up_w path
__global__ __launch_bounds__(256)
void patch_kernel(const float* __restrict__ X, const float* __restrict__ upw,
                  const float* __restrict__ upb, h16* __restrict__ hh)
{
    const int b = blockIdx.x >> 10;
    const int j = blockIdx.x & (ZCAP - 1);
    const unsigned nz = min(g_nz[b], (unsigned)ZCAP);
    if (j >= (int)nz) return;
    const int h0 = g_zlist[b * ZCAP + j];

    __shared__ float w[DD];
    const int tid = threadIdx.x, lane = tid & 31, wid = tid >> 5;
    for (int k = tid; k < DD; k += 256) w[k] = upw[(size_t)h0 * DD + k];
    __syncthreads();
    const float bv = upb[h0];

    for (int s = wid; s < SS; s += 8) {
        const float* row = X + ((size_t)b * SS + s) * DD;
        float p = 0.f;
        for (int k = lane; k < DD; k += 32) p += row[k] * w[k];
        #pragma unroll
        for (int o = 16; o >= 1; o >>= 1)
            p += __shfl_xor_sync(0xFFFFFFFFu, p, o);
        if (lane == 0) {
            float v = p + bv;
            v = v / (1.f + expf(-v));
            hh[((size_t)b * SS + s) * HH + h0] = __float2half_rn(v);
        }
    }
}

// ---------------- launch ----------------
extern "C" void kernel_launch(void* const* d_in, const int* in_sizes, int n_in,
                              void* d_out, int out_size)
{
    (void)in_sizes; (void)n_in; (void)out_size;
    const float* inputs  = (const float*)d_in[0];
    const float* up_w    = (const float*)d_in[1];
    const float* up_b    = (const float*)d_in[2];
    const float* gate_w1 = (const float*)d_in[3];
    const float* gate_b1 = (const float*)d_in[4];
    const float* gate_w2 = (const float*)d_in[5];
    const float* gate_b2 = (const float*)d_in[6];
    const float* mod_w   = (const float*)d_in[7];
    const float* mod_b   = (const float*)d_in[8];
    const float* down_w  = (const float*)d_in[9];
    const float* down_b  = (const float*)d_in[10];
    float* out = (float*)d_out;

    float* s2;
    h16 *xh, *xl, *w1f, *w2f, *s1h, *s1l, *mdf, *dwf, *hh;
    cudaGetSymbolAddress((void**)&s2,  g_s2);
    cudaGetSymbolAddress((void**)&xh,  g_xh);
    cudaGetSymbolAddress((void**)&xl,  g_xl);
    cudaGetSymbolAddress((void**)&w1f, g_w1f);
    cudaGetSymbolAddress((void**)&w2f, g_w2f);
    cudaGetSymbolAddress((void**)&s1h, g_s1h);
    cudaGetSymbolAddress((void**)&s1l, g_s1l);
    cudaGetSymbolAddress((void**)&mdf, g_mdf);
    cudaGetSymbolAddress((void**)&dwf, g_dwf);
    cudaGetSymbolAddress((void**)&hh,  g_hh);

    const int SM2 = 2 * (2 * CTM * TROW + 1 * CTN * TROW);   // 184320
    const int SM1 = 2 * (1 * CTM * TROW + 1 * CTN * TROW);   // 110592
    cudaFuncSetAttribute(mma_gemm<0, 2>, cudaFuncAttributeMaxDynamicSharedMemorySize, SM2);
    cudaFuncSetAttribute(mma_gemm<3, 1>, cudaFuncAttributeMaxDynamicSharedMemorySize, SM1);
    cudaFuncSetAttribute(mma_gemm<2, 1>, cudaFuncAttributeMaxDynamicSharedMemorySize, SM1);
    cudaFuncSetAttribute(mma_gemm<1, 1>, cudaFuncAttributeMaxDynamicSharedMemorySize, SM1);

    cvtp_kernel<<<(MM * DD) / 1024, 256>>>(inputs, xh, xl);       // 0
    cvt1_kernel<<<(HH * DD) / 1024, 256>>>(gate_w1, w1f);         // 1
    cvt1_kernel<<<(HH * HH) / 1024, 256>>>(gate_w2, w2f);         // 2
    select_init_kernel<<<BB * HH / 256, 256>>>();                 // 3

    // G1: scores1 = relu(X @ W1^T + b1) -> fp16 pair (2-term)
    mma_gemm<0, 2><<<(MM / CTM) * (HH / CTN), 256, SM2>>>(        // 4
        xh, xl, w1f, gate_b1, s1h, s1l, HH, DD);

    // G2: scores2 -> fp32 + fused colmax + fused 12-bit radix pass-1 (1-term)
    mma_gemm<3, 1><<<(MM / CTM) * (HH / CTN), 256, SM1>>>(        // 5 <- ncu
        s1h, nullptr, w2f, gate_b2, s2, nullptr, HH, HH);

    cvt1_kernel<<<(HH * DD) / 1024, 256>>>(mod_w, mdf);
    cvt1_kernel<<<(DD * HH) / 1024, 256>>>(down_w, dwf);

    // G4-base: h = silu(X @ mod_w^T + mod_b), all columns (mask-free)
    mma_gemm<2, 1><<<(MM / CTM) * (HH / CTN), 256, SM1>>>(
        xh, nullptr, mdf, mod_b, hh, nullptr, HH, DD);

    // selection: 12-bit pass 1 fused in G2; one full pass for bits [8:20)
    scan12_kernel<<<BB, 256>>>(0);
    { dim3 grid(NPB / 16384, BB); hist12_kernel<<<grid, 256>>>(s2); }
    scan12_kernel<<<BB, 256>>>(1);
    flag_kernel<<<BB * HH / 256, 256>>>();
    refine_kernel<<<BB * NBCAP, 1024>>>(s1h, s1l, gate_w2, gate_b2);
    zlist_kernel<<<BB * HH / 256, 256>>>();
    patch_kernel<<<BB * ZCAP, 256>>>(inputs, up_w, up_b, hh);

    // G5: out = h @ Wd^T + bd -> fp32 (1-term)
    mma_gemm<1, 1><<<(MM / CTM) * (DD / CTN), 256, SM1>>>(
        hh, nullptr, dwf, down_b, out, nullptr, DD, HH);
}

// round 15
// speedup vs baseline: 1.1394x; 1.1056x over previous
#include <cuda_runtime.h>
#include <cuda_fp16.h>
#include <stdint.h>
#include <math.h>

#define BB 8
#define SS 1024
#define DD 1024
#define HH 4096
#define MM (BB*SS)
#define K_SEL 1048576u
#define NPB (SS*HH)
#define NBCAP 64
#define RMARG 1.0e-3f
#define NBIN 4096

typedef __half h16;

// ---------------- device scratch ----------------
__device__ float g_s2[(size_t)MM * HH];
__device__ h16 g_xh[(size_t)MM * DD], g_xl[(size_t)MM * DD];
__device__ h16 g_w1f[(size_t)HH * DD];
__device__ h16 g_w2f[(size_t)HH * HH];
__device__ h16 g_s1h[(size_t)MM * HH], g_s1l[(size_t)MM * HH];
__device__ h16 g_upf[(size_t)HH * DD];
__device__ h16 g_mdf[(size_t)HH * DD];
__device__ h16 g_dwf[(size_t)DD * HH];
__device__ h16 g_hh[(size_t)MM * HH];
__device__ unsigned g_colmax_u[BB * HH];
__device__ unsigned g_hist[BB * NBIN];
__device__ unsigned g_prefix[BB], g_rank[BB], g_nb[BB];
__device__ int g_blist[BB * NBCAP];
__device__ unsigned char g_mask[BB * HH];

// ---------------- PTX helpers (sm_80+ base target only) ----------------
__device__ __forceinline__ uint32_t smem_u32(const void* p) {
    uint32_t a;
    asm("{ .reg .u64 t; cvta.to.shared.u64 t, %1; cvt.u32.u64 %0, t; }"
        : "=r"(a) : "l"(p));
    return a;
}
#define CPA16(dst, src) asm volatile("cp.async.cg.shared.global [%0], [%1], 16;" :: "r"(dst), "l"(src))
#define CPA_COMMIT() asm volatile("cp.async.commit_group;" ::: "memory")
#define CPA_WAIT(N)  asm volatile("cp.async.wait_group %0;" :: "n"(N) : "memory")

__device__ __forceinline__ void ldsm4(uint32_t* r, uint32_t addr) {
    asm volatile("ldmatrix.sync.aligned.m8n8.x4.shared.b16 {%0,%1,%2,%3}, [%4];"
        : "=r"(r[0]), "=r"(r[1]), "=r"(r[2]), "=r"(r[3]) : "r"(addr));
}
__device__ __forceinline__ void mma_h(float* d, const uint32_t* a,
                                      uint32_t b0, uint32_t b1) {
    asm volatile("mma.sync.aligned.m16n8k16.row.col.f32.f16.f16.f32 "
        "{%0,%1,%2,%3}, {%4,%5,%6,%7}, {%8,%9}, {%0,%1,%2,%3};"
        : "+f"(d[0]), "+f"(d[1]), "+f"(d[2]), "+f"(d[3])
        : "r"(a[0]), "r"(a[1]), "r"(a[2]), "r"(a[3]), "r"(b0), "r"(b1));
}
__device__ __forceinline__ unsigned f2u(float f) {
    unsigned u = __float_as_uint(f);
    return (u & 0x80000000u) ? ~u : (u | 0x80000000u);
}
__device__ __forceinline__ float u2f(unsigned v) {
    unsigned u = (v & 0x80000000u) ? (v & 0x7FFFFFFFu) : ~v;
    return __uint_as_float(u);
}

// ---------------- HMMA fp16 split NT GEMM ----------------
// TERMS=1: Ah*Bh   TERMS=2: (Ah+Al)*Bh
// MODE 0: relu(c+bias) -> fp16 pair
// MODE 1: c+bias -> fp32
// MODE 2: mask-select B/bias, silu -> fp16
// MODE 3: MODE 1 + fused colmax atomicMax + fused 12-bit radix pass-1
#define CTM 256
#define CTN 128
#define BKC 64
#define TROW 144

template<int MODE, int TERMS>
__global__ __launch_bounds__(256)
void mma_gemm(const h16* __restrict__ Ah, const h16* __restrict__ Al,
              const h16* __restrict__ Bh,
              const h16* __restrict__ B2h,
              const float* __restrict__ bias, const float* __restrict__ bias2,
              void* __restrict__ C0, void* __restrict__ C1,
              int Ndim, int Kdim, const unsigned char* __restrict__ gmask)
{
    constexpr int NA = (TERMS >= 2) ? 2 : 1;
    constexpr int TILE_A = CTM * TROW;
    constexpr int TILE_B = CTN * TROW;
    constexpr int STAGE = NA * TILE_A + TILE_B;
    extern __shared__ __align__(128) char smem[];
    const uint32_t sb = smem_u32(smem);
    const int tid = threadIdx.x;
    const int lane = tid & 31, wid = tid >> 5;
    const int wm = (wid & 3) * 64;
    const int wn = (wid >> 2) * 64;

    const int tiles_n = Ndim / CTN;
    const int per = 8 * tiles_n;
    const int bid = blockIdx.x;
    const int mi = (bid / per) * 8 + (bid % per) % 8;
    const int ni = (bid % per) / 8;
    const int bm = mi * CTM, bn = ni * CTN;

    const unsigned char* mrow =
        (MODE == 2) ? (gmask + (size_t)(bm >> 10) * HH) : nullptr;

    float acc[4][8][4];
    #pragma unroll
    for (int i = 0; i < 4; i++)
        #pragma unroll
        for (int j = 0; j < 8; j++)
            #pragma unroll
            for (int q = 0; q < 4; q++) acc[i][j][q] = 0.f;

    auto loadA = [&](int s, int k0, const h16* P, int half) {
        const uint32_t base = sb + s * STAGE + half * TILE_A;
        #pragma unroll
        for (int it = 0; it < 8; it++) {
            const int idx = tid + it * 256;
            const int row = idx >> 3, c = idx & 7;
            CPA16(base + row * TROW + c * 16,
                  P + (size_t)(bm + row) * Kdim + k0 + c * 8);
        }
    };
    auto loadB = [&](int s, int k0, const h16* P, const h16* P2) {
        const uint32_t base = sb + s * STAGE + NA * TILE_A;
        #pragma unroll
        for (int it = 0; it < 4; it++) {
            const int idx = tid + it * 256;
            const int row = idx >> 3, c = idx & 7;
            const h16* pb = P;
            if (MODE == 2) { if (mrow[bn + row]) pb = P2; }
            CPA16(base + row * TROW + c * 16,
                  pb + (size_t)(bn + row) * Kdim + k0 + c * 8);
        }
    };
    auto loadStage = [&](int s, int k0) {
        loadA(s, k0, Ah, 0);
        if (TERMS >= 2) loadA(s, k0, Al, 1);
        loadB(s, k0, Bh, B2h);
        CPA_COMMIT();
    };

    const int rsel = lane & 15;
    const int csel = lane >> 4;
    const int C = Kdim / BKC;
    loadStage(0, 0);

    for (int c = 0; c < C; c++) {
        const int s = c & 1;
        if (c + 1 < C) { loadStage(s ^ 1, (c + 1) * BKC); CPA_WAIT(1); }
        else           { CPA_WAIT(0); }
        __syncthreads();

        const uint32_t aH = sb + s * STAGE;
        const uint32_t bH = aH + NA * TILE_A;

        #pragma unroll
        for (int kk = 0; kk < 4; kk++) {
            const int c0 = kk * 2;
            uint32_t af[4][4], bfr[4][4];
            #pragma unroll
            for (int i = 0; i < 4; i++)
                ldsm4(af[i], aH + (uint32_t)((wm + i * 16 + rsel) * TROW + (c0 + csel) * 16));
            #pragma unroll
            for (int g = 0; g < 4; g++)
                ldsm4(bfr[g], bH + (uint32_t)((wn + g * 16 + rsel) * TROW + (c0 + csel) * 16));
            #pragma unroll
            for (int i = 0; i < 4; i++)
                #pragma unroll
                for (int g = 0; g < 4; g++) {
                    mma_h(acc[i][g * 2 + 0], af[i], bfr[g][0], bfr[g][2]);
                    mma_h(acc[i][g * 2 + 1], af[i], bfr[g][1], bfr[g][3]);
                }
            if (TERMS >= 2) {
                uint32_t af2[4][4];
                #pragma unroll
                for (int i = 0; i < 4; i++)
                    ldsm4(af2[i], aH + TILE_A + (uint32_t)((wm + i * 16 + rsel) * TROW + (c0 + csel) * 16));
                #pragma unroll
                for (int i = 0; i < 4; i++)
                    #pragma unroll
                    for (int g = 0; g < 4; g++) {
                        mma_h(acc[i][g * 2 + 0], af2[i], bfr[g][0], bfr[g][2]);
                        mma_h(acc[i][g * 2 + 1], af2[i], bfr[g][1], bfr[g][3]);
                    }
            }
        }
        __syncthreads();
    }

    // ---------------- epilogue ----------------
    unsigned* shist = (unsigned*)smem;   // 4096 bins (16KB) reuse stage smem
    if (MODE == 3) {
        for (int i = tid; i < NBIN; i += 256) shist[i] = 0u;
        __syncthreads();
    }

    const int t4 = lane >> 2;
    const int tn2 = (lane & 3) * 2;
    #pragma unroll
    for (int i = 0; i < 4; i++) {
        #pragma unroll
        for (int j = 0; j < 8; j++) {
            const int m = bm + wm + i * 16 + t4;
            const int n = bn + wn + j * 8 + tn2;
            float d0 = acc[i][j][0], d1 = acc[i][j][1];
            float d2 = acc[i][j][2], d3 = acc[i][j][3];
            if (MODE == 1 || MODE == 3) {
                const float b0 = __ldg(bias + n), b1 = __ldg(bias + n + 1);
                float v0 = d0 + b0, v1 = d1 + b1, v2 = d2 + b0, v3 = d3 + b1;
                float* o0 = (float*)C0 + (size_t)m * Ndim + n;
                float* o1 = (float*)C0 + (size_t)(m + 8) * Ndim + n;
                *(float2*)o0 = make_float2(v0, v1);
                *(float2*)o1 = make_float2(v2, v3);
                if (MODE == 3) {
                    atomicAdd(&shist[f2u(v0) >> 20], 1u);
                    atomicAdd(&shist[f2u(v1) >> 20], 1u);
                    atomicAdd(&shist[f2u(v2) >> 20], 1u);
                    atomicAdd(&shist[f2u(v3) >> 20], 1u);
                }
            } else {
                float b0, b1;
                if (MODE == 0) {
                    b0 = __ldg(bias + n); b1 = __ldg(bias + n + 1);
                } else {
                    const bool q0 = mrow[n] != 0, q1 = mrow[n + 1] != 0;
                    b0 = q0 ? __ldg(bias2 + n)     : __ldg(bias + n);
                    b1 = q1 ? __ldg(bias2 + n + 1) : __ldg(bias + n + 1);
                }
                float v0 = d0 + b0, v1 = d1 + b1, v2 = d2 + b0, v3 = d3 + b1;
                if (MODE == 0) {
                    v0 = fmaxf(v0, 0.f); v1 = fmaxf(v1, 0.f);
                    v2 = fmaxf(v2, 0.f); v3 = fmaxf(v3, 0.f);
                } else {
                    v0 = v0 / (1.f + expf(-v0)); v1 = v1 / (1.f + expf(-v1));
                    v2 = v2 / (1.f + expf(-v2)); v3 = v3 / (1.f + expf(-v3));
                }
                h16 h0 = __float2half_rn(v0), h1 = __float2half_rn(v1);
                h16 h2 = __float2half_rn(v2), h3 = __float2half_rn(v3);
                h16* oh0 = (h16*)C0 + (size_t)m * Ndim + n;
                h16* oh1 = (h16*)C0 + (size_t)(m + 8) * Ndim + n;
                *(__half2*)oh0 = __halves2half2(h0, h1);
                *(__half2*)oh1 = __halves2half2(h2, h3);
                if (MODE == 0) {
                    h16 l0 = __float2half_rn(v0 - __half2float(h0));
                    h16 l1 = __float2half_rn(v1 - __half2float(h1));
                    h16 l2 = __float2half_rn(v2 - __half2float(h2));
                    h16 l3 = __float2half_rn(v3 - __half2float(h3));
                    h16* ol0 = (h16*)C1 + (size_t)m * Ndim + n;
                    h16* ol1 = (h16*)C1 + (size_t)(m + 8) * Ndim + n;
                    *(__half2*)ol0 = __halves2half2(l0, l1);
                    *(__half2*)ol1 = __halves2half2(l2, l3);
                }
            }
        }
    }

    if (MODE == 3) {
        const int b = bm >> 10;
        __syncthreads();
        for (int i = tid; i < NBIN; i += 256)
            if (shist[i]) atomicAdd(&g_hist[b * NBIN + i], shist[i]);
        #pragma unroll
        for (int j = 0; j < 8; j++) {
            const int n = bn + wn + j * 8 + tn2;
            #pragma unroll
            for (int q = 0; q < 2; q++) {
                float vmax = -3.4e38f;
                #pragma unroll
                for (int i = 0; i < 4; i++)
                    vmax = fmaxf(vmax, fmaxf(acc[i][j][q], acc[i][j][q + 2]));
                vmax += __ldg(bias + n + q);
                #pragma unroll
                for (int o = 4; o <= 16; o <<= 1)
                    vmax = fmaxf(vmax, __shfl_xor_sync(0xFFFFFFFFu, vmax, o));
                if (t4 == 0)
                    atomicMax(&g_colmax_u[b * HH + n + q], f2u(vmax));
            }
        }
    }
}

// ---------------- conversion kernels ----------------
__global__ void cvtp_kernel(const float* __restrict__ s,
                            h16* __restrict__ dh, h16* __restrict__ dl) {
    const int i = (blockIdx.x * 256 + threadIdx.x) * 4;
    float4 v = *(const float4*)(s + i);
    h16 a0 = __float2half_rn(v.x), a1 = __float2half_rn(v.y);
    h16 a2 = __float2half_rn(v.z), a3 = __float2half_rn(v.w);
    *(__half2*)(dh + i)     = __halves2half2(a0, a1);
    *(__half2*)(dh + i + 2) = __halves2half2(a2, a3);
    *(__half2*)(dl + i)     = __halves2half2(
        __float2half_rn(v.x - __half2float(a0)),
        __float2half_rn(v.y - __half2float(a1)));
    *(__half2*)(dl + i + 2) = __halves2half2(
        __float2half_rn(v.z - __half2float(a2)),
        __float2half_rn(v.w - __half2float(a3)));
}
__global__ void cvt1_kernel(const float* __restrict__ s, h16* __restrict__ d) {
    const int i = (blockIdx.x * 256 + threadIdx.x) * 4;
    float4 v = *(const float4*)(s + i);
    *(__half2*)(d + i)     = __halves2half2(__float2half_rn(v.x), __float2half_rn(v.y));
    *(__half2*)(d + i + 2) = __halves2half2(__float2half_rn(v.z), __float2half_rn(v.w));
}

// ---------------- selection machinery ----------------
__global__ void select_init_kernel() {
    const int t = blockIdx.x * 256 + threadIdx.x;   // BB*HH = BB*NBIN threads
    if (t < BB * HH) g_colmax_u[t] = 0u;
    if (t < BB * NBIN) g_hist[t] = 0u;
    if (t < BB) { g_prefix[t] = 0u; g_rank[t] = K_SEL; g_nb[t] = 0u; }
}

// pass-2 histogram: bits [8:20) of elements whose top-12 bits match prefix
__global__ void hist12_kernel(const float* __restrict__ s2) {
    __shared__ unsigned sh[NBIN];
    const int b = blockIdx.y;
    const int tid = threadIdx.x;
    for (int i = tid; i < NBIN; i += 256) sh[i] = 0u;
    __syncthreads();
    const unsigned pref = g_prefix[b];
    const float* p = s2 + (size_t)b * NPB;
    const int base = blockIdx.x * 16384;
    #pragma unroll
    for (int i = 0; i < 64; i++) {
        const unsigned u = f2u(p[base + i * 256 + tid]);
        if ((u >> 20) == pref) atomicAdd(&sh[(u >> 8) & 0xFFFu], 1u);
    }
    __syncthreads();
    for (int i = tid; i < NBIN; i += 256)
        if (sh[i]) atomicAdd(&g_hist[b * NBIN + i], sh[i]);
}

// parallel digit select over 4096 bins (grid BB, 256 thr, 16 bins/thread)
__global__ void scan12_kernel(int final) {
    __shared__ unsigned csum[256];
    __shared__ int dsel;
    const int b = blockIdx.x, t = threadIdx.x;
    unsigned loc[16], s = 0;
    const int base = b * NBIN + t * 16;
    #pragma unroll
    for (int i = 0; i < 16; i++) { loc[i] = g_hist[base + i]; s += loc[i]; }
    csum[t] = s;
    if (t == 0) dsel = -1;
    __syncthreads();
    for (int off = 1; off < 256; off <<= 1) {
        unsigned add = (t + off < 256) ? csum[t + off] : 0u;
        __syncthreads();
        csum[t] += add;
        __syncthreads();
    }
    const unsigned r = g_rank[b];
    const unsigned above = (t + 1 < 256) ? csum[t + 1] : 0u;
    unsigned run = above;
    int mydi = -1; unsigned mysub = 0;
    for (int i = 15; i >= 0; i--) {
        run += loc[i];
        if (run >= r) { mydi = i; mysub = run - loc[i]; break; }
    }
    if (mydi >= 0) atomicMax(&dsel, t * 16 + mydi);
    __syncthreads();
    if (mydi >= 0 && t * 16 + mydi == dsel) {
        g_rank[b] = r - mysub;
        if (final) g_prefix[b] = ((g_prefix[b] << 12) | (unsigned)dsel) << 8;
        else       g_prefix[b] = (unsigned)dsel;
    }
    #pragma unroll
    for (int i = 0; i < 16; i++) g_hist[base + i] = 0u;
}

// provisional mask + borderline flagging (g_prefix = final 24-bit tu)
__global__ void flag_kernel() {
    const int i = blockIdx.x * 256 + threadIdx.x;
    const int b = i >> 12;
    const unsigned tu = g_prefix[b];
    const unsigned cu = g_colmax_u[i];
    g_mask[i] = (cu >= tu) ? (unsigned char)1 : (unsigned char)0;
    if (fabsf(u2f(cu) - u2f(tu)) < RMARG) {
        const unsigned idx = atomicAdd(&g_nb[b], 1u);
        if (idx < NBCAP) g_blist[b * NBCAP + idx] = i & (HH - 1);
    }
}

// exact fp32 recompute of borderline columns
__global__ __launch_bounds__(1024)
void refine_kernel(const h16* __restrict__ s1h, const h16* __restrict__ s1l,
                   const float* __restrict__ w2, const float* __restrict__ b2)
{
    const int b = blockIdx.x / NBCAP;
    const int j = blockIdx.x % NBCAP;
    const unsigned nb = min(g_nb[b], (unsigned)NBCAP);
    if (j >= (int)nb) return;
    const int h = g_blist[b * NBCAP + j];

    __shared__ float w2s[HH];
    __shared__ float wmax[32];
    const int tid = threadIdx.x;
    const int lane = tid & 31, wid = tid >> 5;
    for (int k = tid; k < HH; k += 1024) w2s[k] = w2[(size_t)h * HH + k];
    __syncthreads();

    float vmax = -3.4e38f;
    for (int s = wid; s < SS; s += 32) {
        const size_t roff = ((size_t)b * SS + s) * HH;
        const __half2* ph = (const __half2*)(s1h + roff);
        const __half2* pl = (const __half2*)(s1l + roff);
        float part = 0.f;
        for (int k2 = lane; k2 < HH / 2; k2 += 32) {
            const __half2 vh = ph[k2], vl = pl[k2];
            part += (__half2float(vh.x) + __half2float(vl.x)) * w2s[k2 * 2];
            part += (__half2float(vh.y) + __half2float(vl.y)) * w2s[k2 * 2 + 1];
        }
        #pragma unroll
        for (int o = 16; o >= 1; o >>= 1)
            part += __shfl_xor_sync(0xFFFFFFFFu, part, o);
        vmax = fmaxf(vmax, part);
    }
    if (lane == 0) wmax[wid] = vmax;
    __syncthreads();
    if (tid == 0) {
        float m = wmax[0];
        #pragma unroll
        for (int w = 1; w < 32; w++) m = fmaxf(m, wmax[w]);
        m += b2[h];
        g_mask[b * HH + h] = (f2u(m) >= g_prefix[b]) ? (unsigned char)1 : (unsigned char)0;
    }
}

// ---------------- launch ----------------
extern "C" void kernel_launch(void* const* d_in, const int* in_sizes, int n_in,
                              void* d_out, int out_size)
{
    (void)in_sizes; (void)n_in; (void)out_size;
    const float* inputs  = (const float*)d_in[0];
    const float* up_w    = (const float*)d_in[1];
    const float* up_b    = (const float*)d_in[2];
    const float* gate_w1 = (const float*)d_in[3];
    const float* gate_b1 = (const float*)d_in[4];
    const float* gate_w2 = (const float*)d_in[5];
    const float* gate_b2 = (const float*)d_in[6];
    const float* mod_w   = (const float*)d_in[7];
    const float* mod_b   = (const float*)d_in[8];
    const float* down_w  = (const float*)d_in[9];
    const float* down_b  = (const float*)d_in[10];
    float* out = (float*)d_out;

    float* s2;
    h16 *xh, *xl, *w1f, *w2f, *s1h, *s1l, *upf, *mdf, *dwf, *hh;
    unsigned char* maskp;
    cudaGetSymbolAddress((void**)&s2,  g_s2);
    cudaGetSymbolAddress((void**)&xh,  g_xh);
    cudaGetSymbolAddress((void**)&xl,  g_xl);
    cudaGetSymbolAddress((void**)&w1f, g_w1f);
    cudaGetSymbolAddress((void**)&w2f, g_w2f);
    cudaGetSymbolAddress((void**)&s1h, g_s1h);
    cudaGetSymbolAddress((void**)&s1l, g_s1l);
    cudaGetSymbolAddress((void**)&upf, g_upf);
    cudaGetSymbolAddress((void**)&mdf, g_mdf);
    cudaGetSymbolAddress((void**)&dwf, g_dwf);
    cudaGetSymbolAddress((void**)&hh,  g_hh);
    cudaGetSymbolAddress((void**)&maskp, g_mask);

    const int SM2 = 2 * (2 * CTM * TROW + 1 * CTN * TROW);   // 184320
    const int SM1 = 2 * (1 * CTM * TROW + 1 * CTN * TROW);   // 110592
    cudaFuncSetAttribute(mma_gemm<0, 2>, cudaFuncAttributeMaxDynamicSharedMemorySize, SM2);
    cudaFuncSetAttribute(mma_gemm<3, 1>, cudaFuncAttributeMaxDynamicSharedMemorySize, SM1);
    cudaFuncSetAttribute(mma_gemm<2, 1>, cudaFuncAttributeMaxDynamicSharedMemorySize, SM1);
    cudaFuncSetAttribute(mma_gemm<1, 1>, cudaFuncAttributeMaxDynamicSharedMemorySize, SM1);

    cvtp_kernel<<<(MM * DD) / 1024, 256>>>(inputs, xh, xl);       // 0
    cvt1_kernel<<<(HH * DD) / 1024, 256>>>(gate_w1, w1f);         // 1
    cvt1_kernel<<<(HH * HH) / 1024, 256>>>(gate_w2, w2f);         // 2
    select_init_kernel<<<BB * HH / 256, 256>>>();                 // 3

    // G1: scores1 = relu(X @ W1^T + b1) -> fp16 pair (2-term)
    mma_gemm<0, 2><<<(MM / CTM) * (HH / CTN), 256, SM2>>>(        // 4
        xh, xl, w1f, nullptr, gate_b1, nullptr, s1h, s1l, HH, DD, nullptr);

    // G2: scores2 -> fp32 + fused colmax + fused 12-bit radix pass-1 (1-term)
    mma_gemm<3, 1><<<(MM / CTM) * (HH / CTN), 256, SM1>>>(        // 5 <- ncu
        s1h, nullptr, w2f, nullptr, gate_b2, nullptr, s2, nullptr, HH, HH, nullptr);

    cvt1_kernel<<<(HH * DD) / 1024, 256>>>(up_w, upf);
    cvt1_kernel<<<(HH * DD) / 1024, 256>>>(mod_w, mdf);
    cvt1_kernel<<<(DD * HH) / 1024, 256>>>(down_w, dwf);

    // selection: 12-bit pass 1 fused in G2; one full pass for bits [8:20)
    scan12_kernel<<<BB, 256>>>(0);
    { dim3 grid(NPB / 16384, BB); hist12_kernel<<<grid, 256>>>(s2); }
    scan12_kernel<<<BB, 256>>>(1);
    flag_kernel<<<BB * HH / 256, 256>>>();
    refine_kernel<<<BB * NBCAP, 1024>>>(s1h, s1l, gate_w2, gate_b2);

    // G4: h = silu(X @ Wsel^T + bsel) -> fp16 (1-term, mask select)
    mma_gemm<2, 1><<<(MM / CTM) * (HH / CTN), 256, SM1>>>(
        xh, nullptr, upf, mdf, up_b, mod_b, hh, nullptr, HH, DD, maskp);

    // G5: out = h @ Wd^T + bd -> fp32 (1-term)
    mma_gemm<1, 1><<<(MM / CTM) * (DD / CTN), 256, SM1>>>(
        hh, nullptr, dwf, nullptr, down_b, nullptr, out, nullptr, DD, HH, nullptr);
}